// round 7
// baseline (speedup 1.0000x reference)
#include <cuda_runtime.h>
#include <cuda_bf16.h>
#include <math.h>

// ---------------------------------------------------------------------------
#define NB      512
#define NA      256
#define CMAX    0.05f
#define NITERS  300
#define NPOW    30
#define NEWT    8       // warm-started, fixed count

__device__ float dRf[(size_t)NB * 128 * 256];   // rows 0..127 of Q, full width
__device__ float dDf[(size_t)NB * 128 * 128];   // Q[128+i][128+j]

// packed f32x2 FMA: acc = q * y + acc (two fp32 lanes in a 64-bit container)
__device__ __forceinline__ void fma2(unsigned long long& acc,
                                     unsigned long long q,
                                     unsigned long long y) {
    asm("fma.rn.f32x2 %0, %1, %2, %3;" : "=l"(acc) : "l"(q), "l"(y), "l"(acc));
}
__device__ __forceinline__ float unpack_sum(unsigned long long a) {
    float lo, hi;
    asm("mov.b64 {%0, %1}, %2;" : "=f"(lo), "=f"(hi) : "l"(a));
    return lo + hi;
}

// ---------------------------------------------------------------------------
// Kernel 1: Q = A^T A  (tiles (0,0),(0,1),(1,1); Q symmetric)
// ---------------------------------------------------------------------------
__global__ __launch_bounds__(256) void qgemm_kernel(const float* __restrict__ A) {
    const int tile = blockIdx.x;
    const int b    = blockIdx.y;
    const int cj   = (tile == 2) ? 128 : 0;
    const int ck   = (tile == 0) ? 0   : 128;

    __shared__ float sA[16][128];
    __shared__ float sB[16][128];

    const int tid = threadIdx.x;
    const int tx  = tid & 15;
    const int ty  = tid >> 4;

    float acc[8][8];
#pragma unroll
    for (int i = 0; i < 8; ++i)
#pragma unroll
        for (int j = 0; j < 8; ++j) acc[i][j] = 0.f;

    const float* __restrict__ Ab = A + (size_t)b * NA * NA;

    for (int ic = 0; ic < NA; ic += 16) {
#pragma unroll
        for (int u = 0; u < 2; ++u) {
            int idx = tid * 8 + u * 4;
            int r   = idx >> 7;
            int cc  = idx & 127;
            *(float4*)&sA[r][cc] = *(const float4*)&Ab[(size_t)(ic + r) * NA + cj + cc];
            *(float4*)&sB[r][cc] = *(const float4*)&Ab[(size_t)(ic + r) * NA + ck + cc];
        }
        __syncthreads();

#pragma unroll
        for (int kk = 0; kk < 16; ++kk) {
            float a8[8], b8[8];
            const float4* pa = (const float4*)&sA[kk][ty * 8];
            const float4* pb = (const float4*)&sB[kk][tx * 8];
            float4 a0 = pa[0], a1 = pa[1];
            float4 b0 = pb[0], b1 = pb[1];
            a8[0]=a0.x; a8[1]=a0.y; a8[2]=a0.z; a8[3]=a0.w;
            a8[4]=a1.x; a8[5]=a1.y; a8[6]=a1.z; a8[7]=a1.w;
            b8[0]=b0.x; b8[1]=b0.y; b8[2]=b0.z; b8[3]=b0.w;
            b8[4]=b1.x; b8[5]=b1.y; b8[6]=b1.z; b8[7]=b1.w;
#pragma unroll
            for (int i = 0; i < 8; ++i)
#pragma unroll
                for (int j = 0; j < 8; ++j)
                    acc[i][j] = fmaf(a8[i], b8[j], acc[i][j]);
        }
        __syncthreads();
    }

#pragma unroll
    for (int i = 0; i < 8; ++i) {
        int row = ty * 8 + i;
        float4 v0 = make_float4(acc[i][0], acc[i][1], acc[i][2], acc[i][3]);
        float4 v1 = make_float4(acc[i][4], acc[i][5], acc[i][6], acc[i][7]);
        if (tile < 2) {
            float* dst = dRf + ((size_t)b * 128 + row) * 256 + ck + tx * 8;
            *(float4*)dst       = v0;
            *(float4*)(dst + 4) = v1;
        } else {
            float* dst = dDf + ((size_t)b * 128 + row) * 128 + tx * 8;
            *(float4*)dst       = v0;
            *(float4*)(dst + 4) = v1;
        }
    }
}

// ---------------------------------------------------------------------------
// Kernel 2: per-batch FISTA. 512 threads, split-K matvec (f32x2), warm Newton.
// ---------------------------------------------------------------------------
#define TPB 512
#define RP 260
#define DP 132
#define SR_ELEMS (128 * RP)
#define SD_ELEMS (128 * DP)
#define SMEM_FLOATS (SR_ELEMS + SD_ELEMS + 256 + 512 + 32)
#define SMEM_BYTES (SMEM_FLOATS * 4)

__device__ __forceinline__ float blk_sum512(float a, float* red, int t) {
#pragma unroll
    for (int o = 16; o > 0; o >>= 1)
        a += __shfl_xor_sync(0xffffffffu, a, o);
    if ((t & 31) == 0) red[t >> 5] = a;
    __syncthreads();
    float r = 0.f;
#pragma unroll
    for (int i = 0; i < 16; ++i) r += red[i];
    __syncthreads();
    return r;
}

// half matvec: thread (u, h) sums 128 terms of g_u; f32x2 on contiguous paths
__device__ __forceinline__ float matvec_half(const float* __restrict__ sR,
                                             const float* __restrict__ sD,
                                             const float* __restrict__ sy,
                                             int u, int h) {
    if (u < 128) {
        // row u of R, half h: contiguous, packed f32x2
        const ulonglong2* __restrict__ qr = (const ulonglong2*)(sR + u * RP) + h * 32;
        const ulonglong2* __restrict__ yy = (const ulonglong2*)sy + h * 32;
        unsigned long long a0 = 0ull, a1 = 0ull, a2 = 0ull, a3 = 0ull;
#pragma unroll
        for (int k = 0; k < 32; k += 2) {
            ulonglong2 q0 = qr[k],     y0 = yy[k];
            ulonglong2 q1 = qr[k + 1], y1 = yy[k + 1];
            fma2(a0, q0.x, y0.x); fma2(a1, q0.y, y0.y);
            fma2(a2, q1.x, y1.x); fma2(a3, q1.y, y1.y);
        }
        return (unpack_sum(a0) + unpack_sum(a1)) + (unpack_sum(a2) + unpack_sum(a3));
    } else if (h == 0) {
        // column u of R (stride RP; lanes consecutive -> conflict-free)
        const float* __restrict__ qc = sR + u;
        const float4* __restrict__ y4 = (const float4*)sy;
        float g0 = 0.f, g1 = 0.f, g2 = 0.f, g3 = 0.f;
#pragma unroll
        for (int k4 = 0; k4 < 32; ++k4) {
            float4 y = y4[k4];
            const int k = k4 * 4;
            g0 = fmaf(qc[(k + 0) * RP], y.x, g0);
            g1 = fmaf(qc[(k + 1) * RP], y.y, g1);
            g2 = fmaf(qc[(k + 2) * RP], y.z, g2);
            g3 = fmaf(qc[(k + 3) * RP], y.w, g3);
        }
        return (g0 + g1) + (g2 + g3);
    } else {
        // row (u-128) of D: contiguous, packed f32x2
        const ulonglong2* __restrict__ dr = (const ulonglong2*)(sD + (u - 128) * DP);
        const ulonglong2* __restrict__ yy = (const ulonglong2*)sy + 32;
        unsigned long long a0 = 0ull, a1 = 0ull, a2 = 0ull, a3 = 0ull;
#pragma unroll
        for (int k = 0; k < 32; k += 2) {
            ulonglong2 q0 = dr[k],     y0 = yy[k];
            ulonglong2 q1 = dr[k + 1], y1 = yy[k + 1];
            fma2(a0, q0.x, y0.x); fma2(a1, q0.y, y0.y);
            fma2(a2, q1.x, y1.x); fma2(a3, q1.y, y1.y);
        }
        return (unpack_sum(a0) + unpack_sum(a1)) + (unpack_sum(a2) + unpack_sum(a3));
    }
}

__global__ __launch_bounds__(TPB) void fista_kernel(float* __restrict__ out) {
    extern __shared__ float sm[];
    float* sR  = sm;
    float* sD  = sm + SR_ELEMS;
    float* sy  = sD + SD_ELEMS;          // 256
    float* sp  = sy + 256;               // 512 partials
    float* red = sp + 512;               // 32

    const int b    = blockIdx.x;
    const int t    = threadIdx.x;
    const int lane = t & 31;
    const int wid  = t >> 5;             // 0..15
    const int u    = t & 255;
    const int h    = t >> 8;             // 0 or 1

    // --- load compressed Q into padded SMEM ---
    {
        const float4* __restrict__ gR = (const float4*)(dRf + (size_t)b * 128 * 256);
        float4* sR4 = (float4*)sR;
        for (int i = t; i < 128 * 64; i += TPB) {
            int r = i >> 6, c = i & 63;
            sR4[r * 65 + c] = gR[i];
        }
        const float4* __restrict__ gD = (const float4*)(dDf + (size_t)b * 128 * 128);
        float4* sD4 = (float4*)sD;
        for (int i = t; i < 128 * 32; i += TPB) {
            int r = i >> 5, c = i & 31;
            sD4[r * 33 + c] = gD[i];
        }
    }
    if (h == 0) sy[u] = 0.0625f;   // 1/sqrt(256)
    __syncthreads();

    // --- power iteration for lambda_max ---
    for (int pi = 0; pi < NPOW; ++pi) {
        sp[t] = matvec_half(sR, sD, sy, u, h);
        __syncthreads();
        float g = sp[u] + sp[u + 256];
        float nr = blk_sum512((h == 0) ? g * g : 0.f, red, t);
        if (h == 0) sy[u] = g * (1.f / (sqrtf(nr) + 1e-12f));
        __syncthreads();
    }
    float s2;
    {
        sp[t] = matvec_half(sR, sD, sy, u, h);
        __syncthreads();
        float g = sp[u] + sp[u + 256];
        float lmax = blk_sum512((h == 0) ? sy[u] * g : 0.f, red, t);
        s2 = 2.f / (2.f * lmax + 1e-12f);
    }

    // --- FISTA ---
    float w_loc[8], y_loc[8];
#pragma unroll
    for (int j = 0; j < 8; ++j) { w_loc[j] = 1.f / 256.f; y_loc[j] = 1.f / 256.f; }
    float tk  = 1.f;
    float tau = 0.f;                 // warm-started root, persists across iters
    if (h == 0) sy[u] = 1.f / 256.f;
    __syncthreads();

#pragma unroll 1
    for (int it = 0; it < NITERS; ++it) {
        sp[t] = matvec_half(sR, sD, sy, u, h);
        __syncthreads();

        if (wid < 8) {   // projection warps: each holds all 256 coords
            float v[8];
#pragma unroll
            for (int j = 0; j < 8; ++j) {
                int c = lane + 32 * j;
                float g = sp[c] + sp[c + 256];
                v[j] = y_loc[j] - s2 * g;
            }

            // bracket via warp min/max
            float mn0 = fminf(fminf(v[0], v[1]), fminf(v[2], v[3]));
            float mn1 = fminf(fminf(v[4], v[5]), fminf(v[6], v[7]));
            float mx0 = fmaxf(fmaxf(v[0], v[1]), fmaxf(v[2], v[3]));
            float mx1 = fmaxf(fmaxf(v[4], v[5]), fmaxf(v[6], v[7]));
            float mn = fminf(mn0, mn1), mx = fmaxf(mx0, mx1);
#pragma unroll
            for (int o = 16; o > 0; o >>= 1) {
                mn = fminf(mn, __shfl_xor_sync(0xffffffffu, mn, o));
                mx = fmaxf(mx, __shfl_xor_sync(0xffffffffu, mx, o));
            }
            float lo = mn - CMAX, hi = mx + CMAX;
            if (!(tau > lo && tau < hi)) tau = 0.5f * (lo + hi);  // warm clamp

            // fixed-count safeguarded Newton (warm-started)
#pragma unroll 1
            for (int nit = 0; nit < NEWT; ++nit) {
                float s0 = 0.f, s1 = 0.f, c0 = 0.f, c1 = 0.f;
#pragma unroll
                for (int j = 0; j < 8; ++j) {
                    float z  = v[j] - tau;
                    float zc = fminf(fmaxf(z, -CMAX), CMAX);
                    float ir = (fabsf(z) < CMAX) ? 1.f : 0.f;
                    if (j & 1) { s1 += zc; c1 += ir; } else { s0 += zc; c0 += ir; }
                }
                float s = s0 + s1, cn = c0 + c1;
#pragma unroll
                for (int o = 16; o > 0; o >>= 1) {
                    s  += __shfl_xor_sync(0xffffffffu, s,  o);
                    cn += __shfl_xor_sync(0xffffffffu, cn, o);
                }
                if (s > 1.f) lo = tau; else hi = tau;
                float tn = (cn >= 1.f) ? tau + __fdividef(s - 1.f, cn)
                                       : 0.5f * (lo + hi);
                if (!(tn > lo && tn < hi)) tn = 0.5f * (lo + hi);
                tau = tn;
            }

            // exact tau from the active set (reference's recompute)
            float sa = 0.f, sk = 0.f, si = 0.f;
#pragma unroll
            for (int j = 0; j < 8; ++j) {
                float z   = v[j] - tau;
                float inr = (fabsf(z) < CMAX) ? 1.f : 0.f;
                sa += inr * v[j];
                sk += ((z >= CMAX) ? 1.f : 0.f) - ((z <= -CMAX) ? 1.f : 0.f);
                si += inr;
            }
#pragma unroll
            for (int o = 16; o > 0; o >>= 1) {
                sa += __shfl_xor_sync(0xffffffffu, sa, o);
                sk += __shfl_xor_sync(0xffffffffu, sk, o);
                si += __shfl_xor_sync(0xffffffffu, si, o);
            }
            float tau2 = (sa + CMAX * sk - 1.f) / fmaxf(si, 1.f);

            // FISTA momentum
            float tn   = 0.5f * (1.f + sqrtf(1.f + 4.f * tk * tk));
            float coef = (tk - 1.f) / tn;
            tk = tn;

            float yn_own = 0.f;
#pragma unroll
            for (int j = 0; j < 8; ++j) {
                float wn = fminf(fmaxf(v[j] - tau2, -CMAX), CMAX);
                float yn = wn + coef * (wn - w_loc[j]);
                w_loc[j] = wn;
                y_loc[j] = yn;
                if (j == wid) yn_own = yn;
            }
            sy[lane + 32 * wid] = yn_own;   // disjoint owner writes
        }
        __syncthreads();
    }

    if (wid < 8) {
        float w_own = w_loc[0];
#pragma unroll
        for (int j = 1; j < 8; ++j) if (j == wid) w_own = w_loc[j];
        out[(size_t)b * 256 + lane + 32 * wid] = w_own;
    }
}

// ---------------------------------------------------------------------------
extern "C" void kernel_launch(void* const* d_in, const int* in_sizes, int n_in,
                              void* d_out, int out_size) {
    const float* A = (const float*)d_in[0];
    float* out = (float*)d_out;

    cudaFuncSetAttribute(fista_kernel,
                         cudaFuncAttributeMaxDynamicSharedMemorySize, SMEM_BYTES);

    qgemm_kernel<<<dim3(3, NB), 256>>>(A);
    fista_kernel<<<NB, TPB, SMEM_BYTES>>>(out);
}

// round 9
// speedup vs baseline: 1.2847x; 1.2847x over previous
#include <cuda_runtime.h>
#include <cuda_bf16.h>
#include <math.h>

// ---------------------------------------------------------------------------
#define NB      512
#define NA      256
#define CMAX    0.05f
#define NITERS  300
#define NPOW    30
#define NEWT    12

__device__ float dRf[(size_t)NB * 128 * 256];   // rows 0..127 of Q, full width
__device__ float dDf[(size_t)NB * 128 * 128];   // Q[128+i][128+j]

// integer warp reduction (sm_80+; single SASS REDUX vs 5-level shfl tree)
__device__ __forceinline__ int rsum_s32(int x) {
    int r;
    asm("redux.sync.add.s32 %0, %1, 0xffffffff;" : "=r"(r) : "r"(x));
    return r;
}

// ---------------------------------------------------------------------------
// Kernel 1: Q = A^T A  (tiles (0,0),(0,1),(1,1); Q symmetric)
// ---------------------------------------------------------------------------
__global__ __launch_bounds__(256) void qgemm_kernel(const float* __restrict__ A) {
    const int tile = blockIdx.x;
    const int b    = blockIdx.y;
    const int cj   = (tile == 2) ? 128 : 0;
    const int ck   = (tile == 0) ? 0   : 128;

    __shared__ float sA[16][128];
    __shared__ float sB[16][128];

    const int tid = threadIdx.x;
    const int tx  = tid & 15;
    const int ty  = tid >> 4;

    float acc[8][8];
#pragma unroll
    for (int i = 0; i < 8; ++i)
#pragma unroll
        for (int j = 0; j < 8; ++j) acc[i][j] = 0.f;

    const float* __restrict__ Ab = A + (size_t)b * NA * NA;

    for (int ic = 0; ic < NA; ic += 16) {
#pragma unroll
        for (int u = 0; u < 2; ++u) {
            int idx = tid * 8 + u * 4;
            int r   = idx >> 7;
            int cc  = idx & 127;
            *(float4*)&sA[r][cc] = *(const float4*)&Ab[(size_t)(ic + r) * NA + cj + cc];
            *(float4*)&sB[r][cc] = *(const float4*)&Ab[(size_t)(ic + r) * NA + ck + cc];
        }
        __syncthreads();

#pragma unroll
        for (int kk = 0; kk < 16; ++kk) {
            float a8[8], b8[8];
            const float4* pa = (const float4*)&sA[kk][ty * 8];
            const float4* pb = (const float4*)&sB[kk][tx * 8];
            float4 a0 = pa[0], a1 = pa[1];
            float4 b0 = pb[0], b1 = pb[1];
            a8[0]=a0.x; a8[1]=a0.y; a8[2]=a0.z; a8[3]=a0.w;
            a8[4]=a1.x; a8[5]=a1.y; a8[6]=a1.z; a8[7]=a1.w;
            b8[0]=b0.x; b8[1]=b0.y; b8[2]=b0.z; b8[3]=b0.w;
            b8[4]=b1.x; b8[5]=b1.y; b8[6]=b1.z; b8[7]=b1.w;
#pragma unroll
            for (int i = 0; i < 8; ++i)
#pragma unroll
                for (int j = 0; j < 8; ++j)
                    acc[i][j] = fmaf(a8[i], b8[j], acc[i][j]);
        }
        __syncthreads();
    }

#pragma unroll
    for (int i = 0; i < 8; ++i) {
        int row = ty * 8 + i;
        float4 v0 = make_float4(acc[i][0], acc[i][1], acc[i][2], acc[i][3]);
        float4 v1 = make_float4(acc[i][4], acc[i][5], acc[i][6], acc[i][7]);
        if (tile < 2) {
            float* dst = dRf + ((size_t)b * 128 + row) * 256 + ck + tx * 8;
            *(float4*)dst       = v0;
            *(float4*)(dst + 4) = v1;
        } else {
            float* dst = dDf + ((size_t)b * 128 + row) * 128 + tx * 8;
            *(float4*)dst       = v0;
            *(float4*)(dst + 4) = v1;
        }
    }
}

// ---------------------------------------------------------------------------
// Kernel 2: per-batch FISTA. 512 threads, split-K matvec, warp projection.
// ---------------------------------------------------------------------------
#define TPB 512
#define RP 260
#define DP 132
#define SR_ELEMS (128 * RP)
#define SD_ELEMS (128 * DP)
#define SMEM_FLOATS (SR_ELEMS + SD_ELEMS + 256 + 512 + 32)
#define SMEM_BYTES (SMEM_FLOATS * 4)

// block reduction over 512 threads (power phase only)
__device__ __forceinline__ float blk_sum512(float a, float* red, int t) {
#pragma unroll
    for (int o = 16; o > 0; o >>= 1)
        a += __shfl_xor_sync(0xffffffffu, a, o);
    if ((t & 31) == 0) red[t >> 5] = a;
    __syncthreads();
    float r = 0.f;
#pragma unroll
    for (int i = 0; i < 16; ++i) r += red[i];
    __syncthreads();
    return r;
}

// half matvec: thread (u, h) sums 128 terms of g_u
__device__ __forceinline__ float matvec_half(const float* __restrict__ sR,
                                             const float* __restrict__ sD,
                                             const float* __restrict__ sy,
                                             int u, int h) {
    float g0 = 0.f, g1 = 0.f, g2 = 0.f, g3 = 0.f;
    const float4* __restrict__ y4 = (const float4*)sy;
    if (u < 128) {
        // row u of R, half h (contiguous float4)
        const float4* __restrict__ qr = (const float4*)(sR + u * RP) + h * 32;
        const float4* __restrict__ yy = y4 + h * 32;
#pragma unroll
        for (int k = 0; k < 32; ++k) {
            float4 q = qr[k], y = yy[k];
            g0 = fmaf(q.x, y.x, g0); g1 = fmaf(q.y, y.y, g1);
            g2 = fmaf(q.z, y.z, g2); g3 = fmaf(q.w, y.w, g3);
        }
    } else if (h == 0) {
        // column u of R (stride RP; lanes consecutive -> conflict-free)
        const float* __restrict__ qc = sR + u;
#pragma unroll
        for (int k4 = 0; k4 < 32; ++k4) {
            float4 y = y4[k4];
            const int k = k4 * 4;
            g0 = fmaf(qc[(k + 0) * RP], y.x, g0);
            g1 = fmaf(qc[(k + 1) * RP], y.y, g1);
            g2 = fmaf(qc[(k + 2) * RP], y.z, g2);
            g3 = fmaf(qc[(k + 3) * RP], y.w, g3);
        }
    } else {
        // row (u-128) of D (contiguous float4)
        const float4* __restrict__ dr = (const float4*)(sD + (u - 128) * DP);
#pragma unroll
        for (int k = 0; k < 32; ++k) {
            float4 q = dr[k], y = y4[k + 32];
            g0 = fmaf(q.x, y.x, g0); g1 = fmaf(q.y, y.y, g1);
            g2 = fmaf(q.z, y.z, g2); g3 = fmaf(q.w, y.w, g3);
        }
    }
    return (g0 + g1) + (g2 + g3);
}

__global__ __launch_bounds__(TPB) void fista_kernel(float* __restrict__ out) {
    extern __shared__ float sm[];
    float* sR  = sm;
    float* sD  = sm + SR_ELEMS;
    float* sy  = sD + SD_ELEMS;          // 256
    float* sp  = sy + 256;               // 512 partials
    float* red = sp + 512;               // 32

    const int b    = blockIdx.x;
    const int t    = threadIdx.x;
    const int lane = t & 31;
    const int wid  = t >> 5;             // 0..15
    const int u    = t & 255;
    const int h    = t >> 8;             // 0 or 1

    // --- load compressed Q into padded SMEM ---
    {
        const float4* __restrict__ gR = (const float4*)(dRf + (size_t)b * 128 * 256);
        float4* sR4 = (float4*)sR;
        for (int i = t; i < 128 * 64; i += TPB) {
            int r = i >> 6, c = i & 63;
            sR4[r * 65 + c] = gR[i];
        }
        const float4* __restrict__ gD = (const float4*)(dDf + (size_t)b * 128 * 128);
        float4* sD4 = (float4*)sD;
        for (int i = t; i < 128 * 32; i += TPB) {
            int r = i >> 5, c = i & 31;
            sD4[r * 33 + c] = gD[i];
        }
    }
    if (h == 0) sy[u] = 0.0625f;   // 1/sqrt(256)
    __syncthreads();

    // --- power iteration for lambda_max ---
    for (int pi = 0; pi < NPOW; ++pi) {
        sp[t] = matvec_half(sR, sD, sy, u, h);
        __syncthreads();
        float g = sp[u] + sp[u + 256];
        float nr = blk_sum512((h == 0) ? g * g : 0.f, red, t);
        if (h == 0) sy[u] = g * (1.f / (sqrtf(nr) + 1e-12f));
        __syncthreads();
    }
    float s2;
    {
        sp[t] = matvec_half(sR, sD, sy, u, h);
        __syncthreads();
        float g = sp[u] + sp[u + 256];
        float lmax = blk_sum512((h == 0) ? sy[u] * g : 0.f, red, t);
        s2 = 2.f / (2.f * lmax + 1e-12f);
    }

    // --- FISTA ---
    float w_loc[8], y_loc[8];
#pragma unroll
    for (int j = 0; j < 8; ++j) { w_loc[j] = 1.f / 256.f; y_loc[j] = 1.f / 256.f; }
    float tk = 1.f;
    if (h == 0) sy[u] = 1.f / 256.f;
    __syncthreads();

#pragma unroll 1
    for (int it = 0; it < NITERS; ++it) {
        sp[t] = matvec_half(sR, sD, sy, u, h);
        __syncthreads();

        if (wid < 8) {   // projection warps: each holds all 256 coords
            float v[8];
#pragma unroll
            for (int j = 0; j < 8; ++j) {
                int c = lane + 32 * j;
                float g = sp[c] + sp[c + 256];
                v[j] = y_loc[j] - s2 * g;
            }

            // bracket via warp min/max
            float mn0 = fminf(fminf(v[0], v[1]), fminf(v[2], v[3]));
            float mn1 = fminf(fminf(v[4], v[5]), fminf(v[6], v[7]));
            float mx0 = fmaxf(fmaxf(v[0], v[1]), fmaxf(v[2], v[3]));
            float mx1 = fmaxf(fmaxf(v[4], v[5]), fmaxf(v[6], v[7]));
            float mn = fminf(mn0, mn1), mx = fmaxf(mx0, mx1);
#pragma unroll
            for (int o = 16; o > 0; o >>= 1) {
                mn = fminf(mn, __shfl_xor_sync(0xffffffffu, mn, o));
                mx = fmaxf(mx, __shfl_xor_sync(0xffffffffu, mx, o));
            }
            float lo = mn - CMAX, hi = mx + CMAX;
            float tau = 0.5f * (lo + hi);

            // fixed-count safeguarded Newton (float shfl for s, REDUX.s32 for cn)
#pragma unroll 1
            for (int nit = 0; nit < NEWT; ++nit) {
                float s0 = 0.f, s1 = 0.f;
                int   ci = 0;
#pragma unroll
                for (int j = 0; j < 8; ++j) {
                    float z  = v[j] - tau;
                    float zc = fminf(fmaxf(z, -CMAX), CMAX);
                    ci += (fabsf(z) < CMAX) ? 1 : 0;
                    if (j & 1) s1 += zc; else s0 += zc;
                }
                float s = s0 + s1;
#pragma unroll
                for (int o = 16; o > 0; o >>= 1)
                    s += __shfl_xor_sync(0xffffffffu, s, o);
                float cn = (float)rsum_s32(ci);
                if (s > 1.f) lo = tau; else hi = tau;
                float tn = (cn >= 1.f) ? tau + __fdividef(s - 1.f, cn)
                                       : 0.5f * (lo + hi);
                if (!(tn > lo && tn < hi)) tn = 0.5f * (lo + hi);
                tau = tn;
            }

            // exact tau at the final active set.
            // With s = sum clip(v - tau), cn = #interior evaluated at tau:
            //   sum_int(v) + c*(k_hi - k_lo) - 1  ==  s + cn*tau - 1
            // so the reference's recompute is exactly:
            //   tau2 = (s + cn*tau - 1) / max(cn, 1)     (cn = 0 case included)
            {
                float s0 = 0.f, s1 = 0.f;
                int   ci = 0;
#pragma unroll
                for (int j = 0; j < 8; ++j) {
                    float z  = v[j] - tau;
                    float zc = fminf(fmaxf(z, -CMAX), CMAX);
                    ci += (fabsf(z) < CMAX) ? 1 : 0;
                    if (j & 1) s1 += zc; else s0 += zc;
                }
                float s = s0 + s1;
#pragma unroll
                for (int o = 16; o > 0; o >>= 1)
                    s += __shfl_xor_sync(0xffffffffu, s, o);
                float cn = (float)rsum_s32(ci);
                tau = (s + cn * tau - 1.f) / fmaxf(cn, 1.f);
            }

            // FISTA momentum
            float tn   = 0.5f * (1.f + sqrtf(1.f + 4.f * tk * tk));
            float coef = (tk - 1.f) / tn;
            tk = tn;

            float yn_own = 0.f;
#pragma unroll
            for (int j = 0; j < 8; ++j) {
                float wn = fminf(fmaxf(v[j] - tau, -CMAX), CMAX);
                float yn = wn + coef * (wn - w_loc[j]);
                w_loc[j] = wn;
                y_loc[j] = yn;
                if (j == wid) yn_own = yn;
            }
            sy[lane + 32 * wid] = yn_own;   // disjoint owner writes
        }
        __syncthreads();
    }

    if (wid < 8) {
        float w_own = w_loc[0];
#pragma unroll
        for (int j = 1; j < 8; ++j) if (j == wid) w_own = w_loc[j];
        out[(size_t)b * 256 + lane + 32 * wid] = w_own;
    }
}

// ---------------------------------------------------------------------------
extern "C" void kernel_launch(void* const* d_in, const int* in_sizes, int n_in,
                              void* d_out, int out_size) {
    const float* A = (const float*)d_in[0];
    float* out = (float*)d_out;

    cudaFuncSetAttribute(fista_kernel,
                         cudaFuncAttributeMaxDynamicSharedMemorySize, SMEM_BYTES);

    qgemm_kernel<<<dim3(3, NB), 256>>>(A);
    fista_kernel<<<NB, TPB, SMEM_BYTES>>>(out);
}

// round 10
// speedup vs baseline: 1.4692x; 1.1436x over previous
#include <cuda_runtime.h>
#include <cuda_bf16.h>
#include <math.h>

// ---------------------------------------------------------------------------
#define NB      512
#define NA      256
#define CMAX    0.05f
#define NITERS  300
#define NPOW    30
#define NEWT    12

__device__ float dRf[(size_t)NB * 128 * 256];   // rows 0..127 of Q, full width
__device__ float dDf[(size_t)NB * 128 * 128];   // Q[128+i][128+j]

// integer warp reductions (sm_80+; single SASS REDUX vs 5-level shfl tree)
__device__ __forceinline__ int rsum_s32(int x) {
    int r;
    asm("redux.sync.add.s32 %0, %1, 0xffffffff;" : "=r"(r) : "r"(x));
    return r;
}
__device__ __forceinline__ int rmin_s32(int x) {
    int r;
    asm("redux.sync.min.s32 %0, %1, 0xffffffff;" : "=r"(r) : "r"(x));
    return r;
}
__device__ __forceinline__ int rmax_s32(int x) {
    int r;
    asm("redux.sync.max.s32 %0, %1, 0xffffffff;" : "=r"(r) : "r"(x));
    return r;
}
// monotone float <-> signed-int order mapping (involution)
__device__ __forceinline__ int f2ord(float x) {
    int i = __float_as_int(x);
    return i ^ ((i >> 31) & 0x7fffffff);
}
__device__ __forceinline__ float ord2f(int i) {
    return __int_as_float(i ^ ((i >> 31) & 0x7fffffff));
}

// ---------------------------------------------------------------------------
// Kernel 1: Q = A^T A  (tiles (0,0),(0,1),(1,1); Q symmetric)
// ---------------------------------------------------------------------------
__global__ __launch_bounds__(256) void qgemm_kernel(const float* __restrict__ A) {
    const int tile = blockIdx.x;
    const int b    = blockIdx.y;
    const int cj   = (tile == 2) ? 128 : 0;
    const int ck   = (tile == 0) ? 0   : 128;

    __shared__ float sA[16][128];
    __shared__ float sB[16][128];

    const int tid = threadIdx.x;
    const int tx  = tid & 15;
    const int ty  = tid >> 4;

    float acc[8][8];
#pragma unroll
    for (int i = 0; i < 8; ++i)
#pragma unroll
        for (int j = 0; j < 8; ++j) acc[i][j] = 0.f;

    const float* __restrict__ Ab = A + (size_t)b * NA * NA;

    for (int ic = 0; ic < NA; ic += 16) {
#pragma unroll
        for (int u = 0; u < 2; ++u) {
            int idx = tid * 8 + u * 4;
            int r   = idx >> 7;
            int cc  = idx & 127;
            *(float4*)&sA[r][cc] = *(const float4*)&Ab[(size_t)(ic + r) * NA + cj + cc];
            *(float4*)&sB[r][cc] = *(const float4*)&Ab[(size_t)(ic + r) * NA + ck + cc];
        }
        __syncthreads();

#pragma unroll
        for (int kk = 0; kk < 16; ++kk) {
            float a8[8], b8[8];
            const float4* pa = (const float4*)&sA[kk][ty * 8];
            const float4* pb = (const float4*)&sB[kk][tx * 8];
            float4 a0 = pa[0], a1 = pa[1];
            float4 b0 = pb[0], b1 = pb[1];
            a8[0]=a0.x; a8[1]=a0.y; a8[2]=a0.z; a8[3]=a0.w;
            a8[4]=a1.x; a8[5]=a1.y; a8[6]=a1.z; a8[7]=a1.w;
            b8[0]=b0.x; b8[1]=b0.y; b8[2]=b0.z; b8[3]=b0.w;
            b8[4]=b1.x; b8[5]=b1.y; b8[6]=b1.z; b8[7]=b1.w;
#pragma unroll
            for (int i = 0; i < 8; ++i)
#pragma unroll
                for (int j = 0; j < 8; ++j)
                    acc[i][j] = fmaf(a8[i], b8[j], acc[i][j]);
        }
        __syncthreads();
    }

#pragma unroll
    for (int i = 0; i < 8; ++i) {
        int row = ty * 8 + i;
        float4 v0 = make_float4(acc[i][0], acc[i][1], acc[i][2], acc[i][3]);
        float4 v1 = make_float4(acc[i][4], acc[i][5], acc[i][6], acc[i][7]);
        if (tile < 2) {
            float* dst = dRf + ((size_t)b * 128 + row) * 256 + ck + tx * 8;
            *(float4*)dst       = v0;
            *(float4*)(dst + 4) = v1;
        } else {
            float* dst = dDf + ((size_t)b * 128 + row) * 128 + tx * 8;
            *(float4*)dst       = v0;
            *(float4*)(dst + 4) = v1;
        }
    }
}

// ---------------------------------------------------------------------------
// Kernel 2: per-batch FISTA. 1024 threads, split-K x4 matvec, REDUX Newton.
// ---------------------------------------------------------------------------
#define TPB 1024
#define RP 260
#define DP 132
#define SR_ELEMS (128 * RP)
#define SD_ELEMS (128 * DP)
#define SMEM_FLOATS (SR_ELEMS + SD_ELEMS + 256 + 1024 + 32)
#define SMEM_BYTES (SMEM_FLOATS * 4)

// block reduction over 1024 threads (power phase only)
__device__ __forceinline__ float blk_sum1024(float a, float* red, int t) {
#pragma unroll
    for (int o = 16; o > 0; o >>= 1)
        a += __shfl_xor_sync(0xffffffffu, a, o);
    if ((t & 31) == 0) red[t >> 5] = a;
    __syncthreads();
    float r = 0.f;
#pragma unroll
    for (int i = 0; i < 32; ++i) r += red[i];
    __syncthreads();
    return r;
}

// quarter matvec: thread (u, h) sums 64 terms of g_u (h = 0..3)
__device__ __forceinline__ float matvec_q(const float* __restrict__ sR,
                                          const float* __restrict__ sD,
                                          const float* __restrict__ sy,
                                          int u, int h) {
    float g0 = 0.f, g1 = 0.f, g2 = 0.f, g3 = 0.f;
    const float4* __restrict__ y4 = (const float4*)sy;
    if (u < 128) {
        // row u of R, quarter h (contiguous float4)
        const float4* __restrict__ qr = (const float4*)(sR + u * RP) + h * 16;
        const float4* __restrict__ yy = y4 + h * 16;
#pragma unroll
        for (int k = 0; k < 16; ++k) {
            float4 q = qr[k], y = yy[k];
            g0 = fmaf(q.x, y.x, g0); g1 = fmaf(q.y, y.y, g1);
            g2 = fmaf(q.z, y.z, g2); g3 = fmaf(q.w, y.w, g3);
        }
    } else if (h < 2) {
        // column u of R, k in [h*64, h*64+64) (stride RP; lanes consecutive)
        const float* __restrict__ qc = sR + u;
#pragma unroll
        for (int k4 = 0; k4 < 16; ++k4) {
            const int kk = h * 16 + k4;
            float4 y = y4[kk];
            const int k = kk * 4;
            g0 = fmaf(qc[(k + 0) * RP], y.x, g0);
            g1 = fmaf(qc[(k + 1) * RP], y.y, g1);
            g2 = fmaf(qc[(k + 2) * RP], y.z, g2);
            g3 = fmaf(qc[(k + 3) * RP], y.w, g3);
        }
    } else {
        // row (u-128) of D, k in [h*64, h*64+64) (contiguous float4)
        const float4* __restrict__ dr =
            (const float4*)(sD + (u - 128) * DP) + (h - 2) * 16;
        const float4* __restrict__ yy = y4 + 32 + (h - 2) * 16;
#pragma unroll
        for (int k = 0; k < 16; ++k) {
            float4 q = dr[k], y = yy[k];
            g0 = fmaf(q.x, y.x, g0); g1 = fmaf(q.y, y.y, g1);
            g2 = fmaf(q.z, y.z, g2); g3 = fmaf(q.w, y.w, g3);
        }
    }
    return (g0 + g1) + (g2 + g3);
}

__global__ __launch_bounds__(TPB, 1) void fista_kernel(float* __restrict__ out) {
    extern __shared__ float sm[];
    float* sR  = sm;
    float* sD  = sm + SR_ELEMS;
    float* sy  = sD + SD_ELEMS;          // 256
    float* sp  = sy + 256;               // 1024 partials
    float* red = sp + 1024;              // 32

    const int b    = blockIdx.x;
    const int t    = threadIdx.x;
    const int lane = t & 31;
    const int wid  = t >> 5;             // 0..31
    const int u    = t & 255;
    const int h    = t >> 8;             // 0..3

    // --- load compressed Q into padded SMEM ---
    {
        const float4* __restrict__ gR = (const float4*)(dRf + (size_t)b * 128 * 256);
        float4* sR4 = (float4*)sR;
        for (int i = t; i < 128 * 64; i += TPB) {
            int r = i >> 6, c = i & 63;
            sR4[r * 65 + c] = gR[i];
        }
        const float4* __restrict__ gD = (const float4*)(dDf + (size_t)b * 128 * 128);
        float4* sD4 = (float4*)sD;
        for (int i = t; i < 128 * 32; i += TPB) {
            int r = i >> 5, c = i & 31;
            sD4[r * 33 + c] = gD[i];
        }
    }
    if (h == 0) sy[u] = 0.0625f;   // 1/sqrt(256)
    __syncthreads();

    // --- power iteration for lambda_max ---
    for (int pi = 0; pi < NPOW; ++pi) {
        sp[t] = matvec_q(sR, sD, sy, u, h);
        __syncthreads();
        float g = (sp[u] + sp[u + 256]) + (sp[u + 512] + sp[u + 768]);
        float nr = blk_sum1024((h == 0) ? g * g : 0.f, red, t);
        if (h == 0) sy[u] = g * (1.f / (sqrtf(nr) + 1e-12f));
        __syncthreads();
    }
    float s2;
    {
        sp[t] = matvec_q(sR, sD, sy, u, h);
        __syncthreads();
        float g = (sp[u] + sp[u + 256]) + (sp[u + 512] + sp[u + 768]);
        float lmax = blk_sum1024((h == 0) ? sy[u] * g : 0.f, red, t);
        s2 = 2.f / (2.f * lmax + 1e-12f);
    }

    // --- FISTA ---
    const float FS   = 67108864.f;          // 2^26 fixed-point scale
    const float FSI  = 1.f / 67108864.f;
    float w_loc[8], y_loc[8];
#pragma unroll
    for (int j = 0; j < 8; ++j) { w_loc[j] = 1.f / 256.f; y_loc[j] = 1.f / 256.f; }
    float tk = 1.f;
    if (h == 0) sy[u] = 1.f / 256.f;
    __syncthreads();

#pragma unroll 1
    for (int it = 0; it < NITERS; ++it) {
        sp[t] = matvec_q(sR, sD, sy, u, h);
        __syncthreads();

        if (wid < 8) {   // projection warps: each holds all 256 coords
            float v[8];
#pragma unroll
            for (int j = 0; j < 8; ++j) {
                int c = lane + 32 * j;
                float g = (sp[c] + sp[c + 256]) + (sp[c + 512] + sp[c + 768]);
                v[j] = y_loc[j] - s2 * g;
            }

            // bracket via REDUX min/max on order-mapped ints
            float mn0 = fminf(fminf(v[0], v[1]), fminf(v[2], v[3]));
            float mn1 = fminf(fminf(v[4], v[5]), fminf(v[6], v[7]));
            float mx0 = fmaxf(fmaxf(v[0], v[1]), fmaxf(v[2], v[3]));
            float mx1 = fmaxf(fmaxf(v[4], v[5]), fmaxf(v[6], v[7]));
            float mn = ord2f(rmin_s32(f2ord(fminf(mn0, mn1))));
            float mx = ord2f(rmax_s32(f2ord(fmaxf(mx0, mx1))));
            float lo = mn - CMAX, hi = mx + CMAX;
            float tau = 0.5f * (lo + hi);

            // fixed-count safeguarded Newton, fixed-point REDUX reductions
#pragma unroll 1
            for (int nit = 0; nit < NEWT; ++nit) {
                float s0 = 0.f, s1 = 0.f;
                int   ci = 0;
#pragma unroll
                for (int j = 0; j < 8; ++j) {
                    float z  = v[j] - tau;
                    float zc = fminf(fmaxf(z, -CMAX), CMAX);
                    ci += (fabsf(z) < CMAX) ? 1 : 0;
                    if (j & 1) s1 += zc; else s0 += zc;
                }
                int  sfix = rsum_s32(__float2int_rn((s0 + s1) * FS));
                int  cni  = rsum_s32(ci);
                float s  = (float)sfix * FSI;
                float cn = (float)cni;
                if (s > 1.f) lo = tau; else hi = tau;
                float tn = (cni >= 1) ? tau + __fdividef(s - 1.f, cn)
                                      : 0.5f * (lo + hi);
                if (!(tn > lo && tn < hi)) tn = 0.5f * (lo + hi);
                tau = tn;
            }

            // exact tau at the final active set (float-exact reduction):
            //   tau2 = (s + cn*tau - 1) / max(cn, 1)
            {
                float s0 = 0.f, s1 = 0.f;
                int   ci = 0;
#pragma unroll
                for (int j = 0; j < 8; ++j) {
                    float z  = v[j] - tau;
                    float zc = fminf(fmaxf(z, -CMAX), CMAX);
                    ci += (fabsf(z) < CMAX) ? 1 : 0;
                    if (j & 1) s1 += zc; else s0 += zc;
                }
                float s = s0 + s1;
#pragma unroll
                for (int o = 16; o > 0; o >>= 1)
                    s += __shfl_xor_sync(0xffffffffu, s, o);
                float cn = (float)rsum_s32(ci);
                tau = (s + cn * tau - 1.f) / fmaxf(cn, 1.f);
            }

            // FISTA momentum
            float tn   = 0.5f * (1.f + sqrtf(1.f + 4.f * tk * tk));
            float coef = (tk - 1.f) / tn;
            tk = tn;

            float yn_own = 0.f;
#pragma unroll
            for (int j = 0; j < 8; ++j) {
                float wn = fminf(fmaxf(v[j] - tau, -CMAX), CMAX);
                float yn = wn + coef * (wn - w_loc[j]);
                w_loc[j] = wn;
                y_loc[j] = yn;
                if (j == wid) yn_own = yn;
            }
            sy[lane + 32 * wid] = yn_own;   // disjoint owner writes
        }
        __syncthreads();
    }

    if (wid < 8) {
        float w_own = w_loc[0];
#pragma unroll
        for (int j = 1; j < 8; ++j) if (j == wid) w_own = w_loc[j];
        out[(size_t)b * 256 + lane + 32 * wid] = w_own;
    }
}

// ---------------------------------------------------------------------------
extern "C" void kernel_launch(void* const* d_in, const int* in_sizes, int n_in,
                              void* d_out, int out_size) {
    const float* A = (const float*)d_in[0];
    float* out = (float*)d_out;

    cudaFuncSetAttribute(fista_kernel,
                         cudaFuncAttributeMaxDynamicSharedMemorySize, SMEM_BYTES);

    qgemm_kernel<<<dim3(3, NB), 256>>>(A);
    fista_kernel<<<NB, TPB, SMEM_BYTES>>>(out);
}

// round 11
// speedup vs baseline: 1.4826x; 1.0091x over previous
#include <cuda_runtime.h>
#include <cuda_bf16.h>
#include <math.h>

// ---------------------------------------------------------------------------
#define NB      512
#define NA      256
#define CMAX    0.05f
#define NITERS  300
#define NPOW    30
#define NEWT    12

__device__ float dRf[(size_t)NB * 128 * 256];   // rows 0..127 of Q, full width
__device__ float dDf[(size_t)NB * 128 * 128];   // Q[128+i][128+j]

// integer warp reductions (sm_80+)
__device__ __forceinline__ int rsum_s32(int x) {
    int r;
    asm("redux.sync.add.s32 %0, %1, 0xffffffff;" : "=r"(r) : "r"(x));
    return r;
}
__device__ __forceinline__ int rmin_s32(int x) {
    int r;
    asm("redux.sync.min.s32 %0, %1, 0xffffffff;" : "=r"(r) : "r"(x));
    return r;
}
__device__ __forceinline__ int rmax_s32(int x) {
    int r;
    asm("redux.sync.max.s32 %0, %1, 0xffffffff;" : "=r"(r) : "r"(x));
    return r;
}
__device__ __forceinline__ int f2ord(float x) {
    int i = __float_as_int(x);
    return i ^ ((i >> 31) & 0x7fffffff);
}
__device__ __forceinline__ float ord2f(int i) {
    return __int_as_float(i ^ ((i >> 31) & 0x7fffffff));
}

// ---------------------------------------------------------------------------
// Kernel 1: Q = A^T A  (tiles (0,0),(0,1),(1,1); Q symmetric)
// ---------------------------------------------------------------------------
__global__ __launch_bounds__(256) void qgemm_kernel(const float* __restrict__ A) {
    const int tile = blockIdx.x;
    const int b    = blockIdx.y;
    const int cj   = (tile == 2) ? 128 : 0;
    const int ck   = (tile == 0) ? 0   : 128;

    __shared__ float sA[16][128];
    __shared__ float sB[16][128];

    const int tid = threadIdx.x;
    const int tx  = tid & 15;
    const int ty  = tid >> 4;

    float acc[8][8];
#pragma unroll
    for (int i = 0; i < 8; ++i)
#pragma unroll
        for (int j = 0; j < 8; ++j) acc[i][j] = 0.f;

    const float* __restrict__ Ab = A + (size_t)b * NA * NA;

    for (int ic = 0; ic < NA; ic += 16) {
#pragma unroll
        for (int u = 0; u < 2; ++u) {
            int idx = tid * 8 + u * 4;
            int r   = idx >> 7;
            int cc  = idx & 127;
            *(float4*)&sA[r][cc] = *(const float4*)&Ab[(size_t)(ic + r) * NA + cj + cc];
            *(float4*)&sB[r][cc] = *(const float4*)&Ab[(size_t)(ic + r) * NA + ck + cc];
        }
        __syncthreads();

#pragma unroll
        for (int kk = 0; kk < 16; ++kk) {
            float a8[8], b8[8];
            const float4* pa = (const float4*)&sA[kk][ty * 8];
            const float4* pb = (const float4*)&sB[kk][tx * 8];
            float4 a0 = pa[0], a1 = pa[1];
            float4 b0 = pb[0], b1 = pb[1];
            a8[0]=a0.x; a8[1]=a0.y; a8[2]=a0.z; a8[3]=a0.w;
            a8[4]=a1.x; a8[5]=a1.y; a8[6]=a1.z; a8[7]=a1.w;
            b8[0]=b0.x; b8[1]=b0.y; b8[2]=b0.z; b8[3]=b0.w;
            b8[4]=b1.x; b8[5]=b1.y; b8[6]=b1.z; b8[7]=b1.w;
#pragma unroll
            for (int i = 0; i < 8; ++i)
#pragma unroll
                for (int j = 0; j < 8; ++j)
                    acc[i][j] = fmaf(a8[i], b8[j], acc[i][j]);
        }
        __syncthreads();
    }

#pragma unroll
    for (int i = 0; i < 8; ++i) {
        int row = ty * 8 + i;
        float4 v0 = make_float4(acc[i][0], acc[i][1], acc[i][2], acc[i][3]);
        float4 v1 = make_float4(acc[i][4], acc[i][5], acc[i][6], acc[i][7]);
        if (tile < 2) {
            float* dst = dRf + ((size_t)b * 128 + row) * 256 + ck + tx * 8;
            *(float4*)dst       = v0;
            *(float4*)(dst + 4) = v1;
        } else {
            float* dst = dDf + ((size_t)b * 128 + row) * 128 + tx * 8;
            *(float4*)dst       = v0;
            *(float4*)(dst + 4) = v1;
        }
    }
}

// ---------------------------------------------------------------------------
// Kernel 2: per-batch FISTA. 1024 threads. Balanced matvec:
//   warps  0..15 : rows 0..127 of R (k-quarters)        -> sp[0..511]
//   warps 16..23 : rows of D (k-halves)                 -> sp[512..767]
//   warps 24..31 : R_ur^T row-major accumulation        -> sp[768..1791]
// All warps issue ~16 LDS.128 -> no straggler.
// ---------------------------------------------------------------------------
#define TPB 1024
#define RP 260
#define DP 132
#define SR_ELEMS (128 * RP)
#define SD_ELEMS (128 * DP)
#define SP_ELEMS 1792
#define SMEM_FLOATS (SR_ELEMS + SD_ELEMS + 256 + SP_ELEMS + 32)
#define SMEM_BYTES (SMEM_FLOATS * 4)

// block reduction over 1024 threads (power phase only)
__device__ __forceinline__ float blk_sum1024(float a, float* red, int t) {
#pragma unroll
    for (int o = 16; o > 0; o >>= 1)
        a += __shfl_xor_sync(0xffffffffu, a, o);
    if ((t & 31) == 0) red[t >> 5] = a;
    __syncthreads();
    float r = 0.f;
#pragma unroll
    for (int i = 0; i < 32; ++i) r += red[i];
    __syncthreads();
    return r;
}

// matvec producer phase: every warp does balanced float4 work
__device__ __forceinline__ void matvec_produce(const float* __restrict__ sR,
                                               const float* __restrict__ sD,
                                               const float* __restrict__ sy,
                                               float* __restrict__ sp,
                                               int wid, int lane) {
    const float4* __restrict__ y4 = (const float4*)sy;
    if (wid < 16) {
        // row u of R, k-quarter q
        const int q = wid >> 2;
        const int u = ((wid & 3) << 5) + lane;
        const float4* __restrict__ qr = (const float4*)(sR + u * RP) + q * 16;
        const float4* __restrict__ yy = y4 + q * 16;
        float g0 = 0.f, g1 = 0.f, g2 = 0.f, g3 = 0.f;
#pragma unroll
        for (int k = 0; k < 16; ++k) {
            float4 qv = qr[k], yv = yy[k];
            g0 = fmaf(qv.x, yv.x, g0); g1 = fmaf(qv.y, yv.y, g1);
            g2 = fmaf(qv.z, yv.z, g2); g3 = fmaf(qv.w, yv.w, g3);
        }
        sp[q * 128 + u] = (g0 + g1) + (g2 + g3);
    } else if (wid < 24) {
        // row ul of D, k-half hh
        const int w2 = wid - 16;
        const int hh = w2 >> 2;
        const int ul = ((w2 & 3) << 5) + lane;
        const float4* __restrict__ dr = (const float4*)(sD + ul * DP) + hh * 16;
        const float4* __restrict__ yy = y4 + 32 + hh * 16;
        float g0 = 0.f, g1 = 0.f, g2 = 0.f, g3 = 0.f;
#pragma unroll
        for (int k = 0; k < 16; ++k) {
            float4 qv = dr[k], yv = yy[k];
            g0 = fmaf(qv.x, yv.x, g0); g1 = fmaf(qv.y, yv.y, g1);
            g2 = fmaf(qv.z, yv.z, g2); g3 = fmaf(qv.w, yv.w, g3);
        }
        sp[512 + hh * 128 + ul] = (g0 + g1) + (g2 + g3);
    } else {
        // R_ur^T: warp w accumulates rows k = 16w..16w+15 into outputs 128+4*lane+j
        const int w = wid - 24;
        const float4* __restrict__ sR4 = (const float4*)sR;
        float4 acc = make_float4(0.f, 0.f, 0.f, 0.f);
        const int k0 = w * 16;
#pragma unroll
        for (int kb = 0; kb < 4; ++kb) {
            float4 yv = y4[(k0 >> 2) + kb];
#pragma unroll
            for (int kk = 0; kk < 4; ++kk) {
                const int k = k0 + kb * 4 + kk;
                float4 qv = sR4[k * 65 + 32 + lane];   // R[k][128+4*lane ..]
                float yk = (kk == 0) ? yv.x : (kk == 1) ? yv.y
                          : (kk == 2) ? yv.z : yv.w;
                acc.x = fmaf(qv.x, yk, acc.x);
                acc.y = fmaf(qv.y, yk, acc.y);
                acc.z = fmaf(qv.z, yk, acc.z);
                acc.w = fmaf(qv.w, yk, acc.w);
            }
        }
        ((float4*)(sp + 768 + w * 128))[lane] = acc;
    }
}

// gather g_c from partials (lane-consecutive reads, conflict-free)
__device__ __forceinline__ float gather_g(const float* __restrict__ sp, int c) {
    if (c < 128) {
        return (sp[c] + sp[128 + c]) + (sp[256 + c] + sp[384 + c]);
    } else {
        const int cl = c - 128;
        float a = sp[512 + cl] + sp[640 + cl];
        float b0 = sp[768 + cl]  + sp[896 + cl];
        float b1 = sp[1024 + cl] + sp[1152 + cl];
        float b2 = sp[1280 + cl] + sp[1408 + cl];
        float b3 = sp[1536 + cl] + sp[1664 + cl];
        return a + ((b0 + b1) + (b2 + b3));
    }
}

__global__ __launch_bounds__(TPB, 1) void fista_kernel(float* __restrict__ out) {
    extern __shared__ float sm[];
    float* sR  = sm;
    float* sD  = sm + SR_ELEMS;
    float* sy  = sD + SD_ELEMS;          // 256
    float* sp  = sy + 256;               // 1792 partials
    float* red = sp + SP_ELEMS;          // 32

    const int b    = blockIdx.x;
    const int t    = threadIdx.x;
    const int lane = t & 31;
    const int wid  = t >> 5;             // 0..31

    // --- load compressed Q into padded SMEM ---
    {
        const float4* __restrict__ gR = (const float4*)(dRf + (size_t)b * 128 * 256);
        float4* sR4 = (float4*)sR;
        for (int i = t; i < 128 * 64; i += TPB) {
            int r = i >> 6, c = i & 63;
            sR4[r * 65 + c] = gR[i];
        }
        const float4* __restrict__ gD = (const float4*)(dDf + (size_t)b * 128 * 128);
        float4* sD4 = (float4*)sD;
        for (int i = t; i < 128 * 32; i += TPB) {
            int r = i >> 5, c = i & 31;
            sD4[r * 33 + c] = gD[i];
        }
    }
    if (t < 256) sy[t] = 0.0625f;   // 1/sqrt(256)
    __syncthreads();

    // --- power iteration for lambda_max ---
    for (int pi = 0; pi < NPOW; ++pi) {
        matvec_produce(sR, sD, sy, sp, wid, lane);
        __syncthreads();
        float g = (t < 256) ? gather_g(sp, t) : 0.f;
        float nr = blk_sum1024((t < 256) ? g * g : 0.f, red, t);
        if (t < 256) sy[t] = g * (1.f / (sqrtf(nr) + 1e-12f));
        __syncthreads();
    }
    float s2;
    {
        matvec_produce(sR, sD, sy, sp, wid, lane);
        __syncthreads();
        float g = (t < 256) ? gather_g(sp, t) : 0.f;
        float lmax = blk_sum1024((t < 256) ? sy[t] * g : 0.f, red, t);
        s2 = 2.f / (2.f * lmax + 1e-12f);
    }

    // --- FISTA ---
    const float FS  = 67108864.f;          // 2^26 fixed-point scale
    const float FSI = 1.f / 67108864.f;
    float w_loc[8], y_loc[8];
#pragma unroll
    for (int j = 0; j < 8; ++j) { w_loc[j] = 1.f / 256.f; y_loc[j] = 1.f / 256.f; }
    float tk = 1.f;
    if (t < 256) sy[t] = 1.f / 256.f;
    __syncthreads();

#pragma unroll 1
    for (int it = 0; it < NITERS; ++it) {
        matvec_produce(sR, sD, sy, sp, wid, lane);
        __syncthreads();

        if (wid < 8) {   // projection warps: each holds all 256 coords
            float v[8];
#pragma unroll
            for (int j = 0; j < 8; ++j) {
                int c = lane + 32 * j;
                v[j] = y_loc[j] - s2 * gather_g(sp, c);
            }

            // bracket via REDUX min/max on order-mapped ints
            float mn0 = fminf(fminf(v[0], v[1]), fminf(v[2], v[3]));
            float mn1 = fminf(fminf(v[4], v[5]), fminf(v[6], v[7]));
            float mx0 = fmaxf(fmaxf(v[0], v[1]), fmaxf(v[2], v[3]));
            float mx1 = fmaxf(fmaxf(v[4], v[5]), fmaxf(v[6], v[7]));
            float mn = ord2f(rmin_s32(f2ord(fminf(mn0, mn1))));
            float mx = ord2f(rmax_s32(f2ord(fmaxf(mx0, mx1))));
            float lo = mn - CMAX, hi = mx + CMAX;
            float tau = 0.5f * (lo + hi);

            // fixed-count safeguarded Newton, fixed-point REDUX reductions
#pragma unroll 1
            for (int nit = 0; nit < NEWT; ++nit) {
                float s0 = 0.f, s1 = 0.f;
                int   ci = 0;
#pragma unroll
                for (int j = 0; j < 8; ++j) {
                    float z  = v[j] - tau;
                    float zc = fminf(fmaxf(z, -CMAX), CMAX);
                    ci += (fabsf(z) < CMAX) ? 1 : 0;
                    if (j & 1) s1 += zc; else s0 += zc;
                }
                int  sfix = rsum_s32(__float2int_rn((s0 + s1) * FS));
                int  cni  = rsum_s32(ci);
                float s  = (float)sfix * FSI;
                float cn = (float)cni;
                if (s > 1.f) lo = tau; else hi = tau;
                float tn = (cni >= 1) ? tau + __fdividef(s - 1.f, cn)
                                      : 0.5f * (lo + hi);
                if (!(tn > lo && tn < hi)) tn = 0.5f * (lo + hi);
                tau = tn;
            }

            // exact tau at the final active set (float-exact reduction):
            //   tau2 = (s + cn*tau - 1) / max(cn, 1)
            {
                float s0 = 0.f, s1 = 0.f;
                int   ci = 0;
#pragma unroll
                for (int j = 0; j < 8; ++j) {
                    float z  = v[j] - tau;
                    float zc = fminf(fmaxf(z, -CMAX), CMAX);
                    ci += (fabsf(z) < CMAX) ? 1 : 0;
                    if (j & 1) s1 += zc; else s0 += zc;
                }
                float s = s0 + s1;
#pragma unroll
                for (int o = 16; o > 0; o >>= 1)
                    s += __shfl_xor_sync(0xffffffffu, s, o);
                float cn = (float)rsum_s32(ci);
                tau = (s + cn * tau - 1.f) / fmaxf(cn, 1.f);
            }

            // FISTA momentum
            float tn   = 0.5f * (1.f + sqrtf(1.f + 4.f * tk * tk));
            float coef = (tk - 1.f) / tn;
            tk = tn;

            float yn_own = 0.f;
#pragma unroll
            for (int j = 0; j < 8; ++j) {
                float wn = fminf(fmaxf(v[j] - tau, -CMAX), CMAX);
                float yn = wn + coef * (wn - w_loc[j]);
                w_loc[j] = wn;
                y_loc[j] = yn;
                if (j == wid) yn_own = yn;
            }
            sy[lane + 32 * wid] = yn_own;   // disjoint owner writes
        }
        __syncthreads();
    }

    if (wid < 8) {
        float w_own = w_loc[0];
#pragma unroll
        for (int j = 1; j < 8; ++j) if (j == wid) w_own = w_loc[j];
        out[(size_t)b * 256 + lane + 32 * wid] = w_own;
    }
}

// ---------------------------------------------------------------------------
extern "C" void kernel_launch(void* const* d_in, const int* in_sizes, int n_in,
                              void* d_out, int out_size) {
    const float* A = (const float*)d_in[0];
    float* out = (float*)d_out;

    cudaFuncSetAttribute(fista_kernel,
                         cudaFuncAttributeMaxDynamicSharedMemorySize, SMEM_BYTES);

    qgemm_kernel<<<dim3(3, NB), 256>>>(A);
    fista_kernel<<<NB, TPB, SMEM_BYTES>>>(out);
}